// round 14
// baseline (speedup 1.0000x reference)
#include <cuda_runtime.h>
#include <cuda_bf16.h>
#include <cstdint>

// B=8, SEQ=4096, DIM=64.
// out = scale * rope(Q) @ (rope(K)^T @ rope(V))   (associativity; no softmax)
// scale = 1/sqrt(64) = 0.125
// Tensor path: mma.sync.m16n8k8 TF32, 2-way split (3 MMAs) for fp32 accuracy.
// R14: k2 deleted (k1 atomically accumulates into g_M); operand splits hoisted
// into staging so GEMM inner loops are pure LDS+MMA.

#define BATCH  8
#define SEQ    4096
#define DIM    64
#define NC1    128         // k1 chunks per batch (32 rows each)
#define CH1    32

__device__ float g_M[BATCH * DIM * DIM];   // 128 KB accumulator

// ---------------------------------------------------------------------------
__device__ __forceinline__ uint32_t f2tf32(float x) {
    uint32_t r; asm("cvt.rna.tf32.f32 %0, %1;" : "=r"(r) : "f"(x)); return r;
}
__device__ __forceinline__ float4 rope4(float4 x, float4 f) {
    float4 o;
    o.x = x.x * f.x - x.y * f.y;  o.y = x.x * f.y + x.y * f.x;
    o.z = x.z * f.z - x.w * f.w;  o.w = x.z * f.w + x.w * f.z;
    return o;
}
__device__ __forceinline__ void mma8(float* c, const uint32_t* a, const uint32_t* b) {
    asm volatile(
        "mma.sync.aligned.m16n8k8.row.col.f32.tf32.tf32.f32 "
        "{%0,%1,%2,%3}, {%4,%5,%6,%7}, {%8,%9}, {%0,%1,%2,%3};\n"
        : "+f"(c[0]), "+f"(c[1]), "+f"(c[2]), "+f"(c[3])
        : "r"(a[0]), "r"(a[1]), "r"(a[2]), "r"(a[3]), "r"(b[0]), "r"(b[1]));
}
__device__ __forceinline__ void split1(float x, uint32_t& hi, uint32_t& lo) {
    hi = f2tf32(x);
    lo = __float_as_uint(x - __uint_as_float(hi));
}
__device__ __forceinline__ void split4(float4 v, float4& h, float4& l) {
    uint32_t h0, l0, h1, l1, h2, l2, h3, l3;
    split1(v.x, h0, l0); split1(v.y, h1, l1);
    split1(v.z, h2, l2); split1(v.w, h3, l3);
    h = make_float4(__uint_as_float(h0), __uint_as_float(h1),
                    __uint_as_float(h2), __uint_as_float(h3));
    l = make_float4(__uint_as_float(l0), __uint_as_float(l1),
                    __uint_as_float(l2), __uint_as_float(l3));
}

// ---------------------------------------------------------------------------
// Kernel 0: zero the global accumulator (runs first in the graph each replay)
// ---------------------------------------------------------------------------
__global__ __launch_bounds__(256) void zero_kernel()
{
    const int o = blockIdx.x * 256 + threadIdx.x;    // 0..8191 float4
    ((float4*)g_M)[o] = make_float4(0.f, 0.f, 0.f, 0.f);
}

// ---------------------------------------------------------------------------
// Kernel 1: g_M[b] += rope(K)^T @ rope(V) over a 32-row chunk (atomic).
// 1024 CTAs x 128 thr, 4 warps; warp w = M rows 16w..16w+15 over all 32 seq
// rows. V pre-split hi/lo in staging (shared across warps); K split in regs.
// Strides 72 (72%32=8): fragment LDS word = 8*tig+g+c -> full permutation.
// ---------------------------------------------------------------------------
__global__ __launch_bounds__(128) void kv_outer_kernel(
    const float* __restrict__ K, const float* __restrict__ V,
    const float* __restrict__ FK, const float* __restrict__ FV)
{
    const int b = blockIdx.y;
    const int c = blockIdx.x;
    const int t = threadIdx.x;
    const int w = t >> 5;
    const int lane = t & 31;
    const int g = lane >> 2;
    const int tig = lane & 3;

    __shared__ float sk [CH1 * 72];   // 9.2 KB raw K
    __shared__ float svh[CH1 * 72];   // 9.2 KB V hi
    __shared__ float svl[CH1 * 72];   // 9.2 KB V lo

    const float4* K4  = (const float4*)(K + (size_t)b * SEQ * DIM);
    const float4* V4  = (const float4*)(V + (size_t)b * SEQ * DIM);
    const float4* FK4 = (const float4*)FK;
    const float4* FV4 = (const float4*)FV;

    // stage 32 rows, rope fused; V split once here (shared by all 4 warps)
#pragma unroll
    for (int u = 0; u < 4; u++) {
        const int f  = t + 128 * u;
        const int rr = f >> 4, cc = f & 15;
        const int gi = (c * CH1 + rr) * 16 + cc;
        *(float4*)&sk[rr * 72 + 4 * cc] = rope4(K4[gi], FK4[gi]);
        float4 vh, vl;
        split4(rope4(V4[gi], FV4[gi]), vh, vl);
        *(float4*)&svh[rr * 72 + 4 * cc] = vh;
        *(float4*)&svl[rr * 72 + 4 * cc] = vl;
    }
    __syncthreads();

    const int m0 = 16 * w;

    float acc[8][4];
#pragma unroll
    for (int j = 0; j < 8; j++)
#pragma unroll
        for (int p = 0; p < 4; p++) acc[j][p] = 0.0f;

#pragma unroll
    for (int ks = 0; ks < 4; ks++) {
        const int krow = 8 * ks;
        uint32_t ah[4], al[4];
        {
            const float a0 = sk[(krow + tig)     * 72 + m0 + g];
            const float a1 = sk[(krow + tig)     * 72 + m0 + g + 8];
            const float a2 = sk[(krow + tig + 4) * 72 + m0 + g];
            const float a3 = sk[(krow + tig + 4) * 72 + m0 + g + 8];
            split1(a0, ah[0], al[0]); split1(a1, ah[1], al[1]);
            split1(a2, ah[2], al[2]); split1(a3, ah[3], al[3]);
        }
#pragma unroll
        for (int j = 0; j < 8; j++) {
            const int n0 = 8 * j;
            uint32_t bh[2], bl[2];
            bh[0] = __float_as_uint(svh[(krow + tig)     * 72 + n0 + g]);
            bh[1] = __float_as_uint(svh[(krow + tig + 4) * 72 + n0 + g]);
            bl[0] = __float_as_uint(svl[(krow + tig)     * 72 + n0 + g]);
            bl[1] = __float_as_uint(svl[(krow + tig + 4) * 72 + n0 + g]);
            mma8(acc[j], ah, bh);
            mma8(acc[j], ah, bl);
            mma8(acc[j], al, bh);
        }
    }

    // atomic accumulate into g_M[b] — replaces the partials + reduce kernels
    float* Mb = g_M + (size_t)b * DIM * DIM;
#pragma unroll
    for (int j = 0; j < 8; j++) {
        const int col = 8 * j + 2 * tig;
        atomicAdd(&Mb[(m0 + g)     * DIM + col],     acc[j][0]);
        atomicAdd(&Mb[(m0 + g)     * DIM + col + 1], acc[j][1]);
        atomicAdd(&Mb[(m0 + g + 8) * DIM + col],     acc[j][2]);
        atomicAdd(&Mb[(m0 + g + 8) * DIM + col + 1], acc[j][3]);
    }
}

// ---------------------------------------------------------------------------
// Kernel 3: out = scale * rope(Q) @ M[b].
// 2048 CTAs x 128 thr: CTA = 32 q-rows x 32-col slice. M slice pre-split
// (stride 40), q pre-split hi/lo (stride 68) -> inner loop is pure LDS+MMA.
// 4 warps: row-half (w&1) x col-sub (w>>1).
// ---------------------------------------------------------------------------
__global__ __launch_bounds__(128) void qm_kernel(
    const float* __restrict__ Q, const float* __restrict__ FQ,
    float* __restrict__ OUT)
{
    const int b   = blockIdx.y;
    const int rc  = blockIdx.x >> 1;      // 32-row chunk
    const int chf = blockIdx.x & 1;       // col half
    const int t   = threadIdx.x;
    const int w   = t >> 5;
    const int lane = t & 31;
    const int g = lane >> 2;
    const int tig = lane & 3;

    __shared__ float sMh[DIM * 40];   // 10.24 KB
    __shared__ float sMl[DIM * 40];   // 10.24 KB
    __shared__ float sqh[CH1 * 68];   // 8.7 KB
    __shared__ float sql[CH1 * 68];   // 8.7 KB

    // ---- load + split M[b] slice: cols [32*chf, 32*chf+32) ----
    {
        const float4* M4 = (const float4*)(g_M + (size_t)b * DIM * DIM);
#pragma unroll
        for (int u = 0; u < 4; u++) {
            const int f  = t + 128 * u;    // 0..511
            const int k  = f >> 3;         // 0..63
            const int n4 = f & 7;
            float4 h, l;
            split4(M4[k * 16 + 8 * chf + n4], h, l);
            *(float4*)&sMh[k * 40 + 4 * n4] = h;
            *(float4*)&sMl[k * 40 + 4 * n4] = l;
        }
    }

    // ---- stage + rope + split 32 q rows ----
    const float4* Q4  = (const float4*)(Q + (size_t)b * SEQ * DIM);
    const float4* FQ4 = (const float4*)FQ;
#pragma unroll
    for (int u = 0; u < 4; u++) {
        const int f  = t + 128 * u;
        const int rr = f >> 4, cc = f & 15;
        const int gi = (rc * CH1 + rr) * 16 + cc;
        float4 h, l;
        split4(rope4(Q4[gi], FQ4[gi]), h, l);
        *(float4*)&sqh[rr * 68 + 4 * cc] = h;
        *(float4*)&sql[rr * 68 + 4 * cc] = l;
    }
    __syncthreads();

    const int m0s  = 16 * (w & 1);
    const int nsub = 16 * (w >> 1);

    float cc2[2][4];
#pragma unroll
    for (int jj = 0; jj < 2; jj++)
#pragma unroll
        for (int p = 0; p < 4; p++) cc2[jj][p] = 0.0f;

#pragma unroll
    for (int ks = 0; ks < 8; ks++) {
        const int k0 = 8 * ks;
        uint32_t ah[4], al[4];
        ah[0] = __float_as_uint(sqh[(m0s + g)     * 68 + k0 + tig]);
        ah[1] = __float_as_uint(sqh[(m0s + g + 8) * 68 + k0 + tig]);
        ah[2] = __float_as_uint(sqh[(m0s + g)     * 68 + k0 + tig + 4]);
        ah[3] = __float_as_uint(sqh[(m0s + g + 8) * 68 + k0 + tig + 4]);
        al[0] = __float_as_uint(sql[(m0s + g)     * 68 + k0 + tig]);
        al[1] = __float_as_uint(sql[(m0s + g + 8) * 68 + k0 + tig]);
        al[2] = __float_as_uint(sql[(m0s + g)     * 68 + k0 + tig + 4]);
        al[3] = __float_as_uint(sql[(m0s + g + 8) * 68 + k0 + tig + 4]);
#pragma unroll
        for (int jj = 0; jj < 2; jj++) {
            const int n0 = nsub + 8 * jj;
            uint32_t bh[2], bl[2];
            bh[0] = __float_as_uint(sMh[(k0 + tig)     * 40 + n0 + g]);
            bh[1] = __float_as_uint(sMh[(k0 + tig + 4) * 40 + n0 + g]);
            bl[0] = __float_as_uint(sMl[(k0 + tig)     * 40 + n0 + g]);
            bl[1] = __float_as_uint(sMl[(k0 + tig + 4) * 40 + n0 + g]);
            mma8(cc2[jj], ah, bh);
            mma8(cc2[jj], ah, bl);
            mma8(cc2[jj], al, bh);
        }
    }

    // ---- write this warp's 16 rows x 16 cols ----
    const float scale = 0.125f;   // 1/sqrt(64)
    float* O = OUT + ((size_t)b * SEQ + rc * CH1) * DIM;
#pragma unroll
    for (int jj = 0; jj < 2; jj++) {
        const int colg = 32 * chf + nsub + 8 * jj + 2 * tig;
        *(float2*)&O[(size_t)(m0s + g)     * DIM + colg] =
            make_float2(cc2[jj][0] * scale, cc2[jj][1] * scale);
        *(float2*)&O[(size_t)(m0s + g + 8) * DIM + colg] =
            make_float2(cc2[jj][2] * scale, cc2[jj][3] * scale);
    }
}

// ---------------------------------------------------------------------------
extern "C" void kernel_launch(void* const* d_in, const int* in_sizes, int n_in,
                              void* d_out, int out_size)
{
    const float* q  = (const float*)d_in[0];
    const float* k  = (const float*)d_in[1];
    const float* v  = (const float*)d_in[2];
    const float* fq = (const float*)d_in[3];
    const float* fk = (const float*)d_in[4];
    const float* fv = (const float*)d_in[5];
    float* out = (float*)d_out;

    zero_kernel<<<32, 256>>>();
    kv_outer_kernel<<<dim3(NC1, BATCH), 128>>>(k, v, fk, fv);
    qm_kernel<<<dim3(256, BATCH), 128>>>(q, fq, out);
}

// round 15
// speedup vs baseline: 1.1394x; 1.1394x over previous
#include <cuda_runtime.h>
#include <cuda_bf16.h>
#include <cstdint>

// B=8, SEQ=4096, DIM=64.
// out = scale * rope(Q) @ (rope(K)^T @ rope(V))   (associativity; no softmax)
// scale = 1/sqrt(64) = 0.125
// Tensor path: mma.sync.m16n8k16 BF16, 2-way split (3 MMAs) -> ~1e-5 accuracy.

#define BATCH  8
#define SEQ    4096
#define DIM    64
#define NC     64          // k1 chunks per batch (64 rows each)
#define CH     64
#define NGRP   8

__device__ float g_partials[NC * BATCH * DIM * DIM];   // 8 MB
__device__ float g_p2[NGRP * BATCH * DIM * DIM];       // 1 MB
__device__ float g_M[BATCH * DIM * DIM];               // 128 KB

// ---------------------------------------------------------------------------
__device__ __forceinline__ float4 rope4(float4 x, float4 f) {
    float4 o;
    o.x = x.x * f.x - x.y * f.y;  o.y = x.x * f.y + x.y * f.x;
    o.z = x.z * f.z - x.w * f.w;  o.w = x.z * f.w + x.w * f.z;
    return o;
}
// bf16 MMA: D(16x8) += A(16x16) * B(16x8)
__device__ __forceinline__ void mma16(float* c, const uint32_t* a, const uint32_t* b) {
    asm volatile(
        "mma.sync.aligned.m16n8k16.row.col.f32.bf16.bf16.f32 "
        "{%0,%1,%2,%3}, {%4,%5,%6,%7}, {%8,%9}, {%0,%1,%2,%3};\n"
        : "+f"(c[0]), "+f"(c[1]), "+f"(c[2]), "+f"(c[3])
        : "r"(a[0]), "r"(a[1]), "r"(a[2]), "r"(a[3]), "r"(b[0]), "r"(b[1]));
}
// pack (x0 -> lo half, x1 -> hi half) as bf16x2; also emit lo-residual word.
__device__ __forceinline__ void pack2(float x0, float x1, uint32_t& h, uint32_t& l) {
    asm("cvt.rn.bf16x2.f32 %0, %1, %2;" : "=r"(h) : "f"(x1), "f"(x0));
    const float u0 = __uint_as_float(h << 16);
    const float u1 = __uint_as_float(h & 0xFFFF0000u);
    const float l0 = x0 - u0;
    const float l1 = x1 - u1;
    asm("cvt.rn.bf16x2.f32 %0, %1, %2;" : "=r"(l) : "f"(l1), "f"(l0));
}

// ---------------------------------------------------------------------------
// Kernel 1: partial M = rope(K)^T @ rope(V) over 64 rows.
// 512 CTAs x 128 thr, 4 warps; warp w = M rows 16w..16w+15 x all 64 cols.
// K packed as A-layout [kp(seq-pair)][dim] stride 72 words (72%32=8 ->
// fragment LDS bank = 8*tig+g: permutation). V packed as B-layout [kp][n],
// same stride. Staging threads own seq ROW-PAIRS so packing is local;
// 4-word contiguous STS.128, conflict-free phases.
// ---------------------------------------------------------------------------
__global__ __launch_bounds__(128) void kv_outer_kernel(
    const float* __restrict__ K, const float* __restrict__ V,
    const float* __restrict__ FK, const float* __restrict__ FV)
{
    const int b = blockIdx.y;
    const int c = blockIdx.x;
    const int t = threadIdx.x;
    const int w = t >> 5;
    const int lane = t & 31;
    const int g = lane >> 2;
    const int tig = lane & 3;

    __shared__ uint32_t skh[32 * 72], skl[32 * 72];   // A hi/lo: 9.2 KB each
    __shared__ uint32_t svh[32 * 72], svl[32 * 72];   // B hi/lo

    const float4* K4  = (const float4*)(K + (size_t)b * SEQ * DIM);
    const float4* V4  = (const float4*)(V + (size_t)b * SEQ * DIM);
    const float4* FK4 = (const float4*)FK;
    const float4* FV4 = (const float4*)FV;

    // staging: 512 items = (32 row-pairs x 16 col4), 4 per thread
#pragma unroll
    for (int u = 0; u < 4; u++) {
        const int f  = t + 128 * u;
        const int rp = f >> 4;          // seq row-pair 0..31
        const int cc = f & 15;          // float4 column
        const int r0 = (c * CH + 2 * rp) * 16 + cc;
        const float4 ka = rope4(K4[r0],      FK4[r0]);
        const float4 kb = rope4(K4[r0 + 16], FK4[r0 + 16]);
        const float4 va = rope4(V4[r0],      FV4[r0]);
        const float4 vb = rope4(V4[r0 + 16], FV4[r0 + 16]);
        uint32_t kh[4], kl[4], vh[4], vl[4];
        pack2(ka.x, kb.x, kh[0], kl[0]); pack2(ka.y, kb.y, kh[1], kl[1]);
        pack2(ka.z, kb.z, kh[2], kl[2]); pack2(ka.w, kb.w, kh[3], kl[3]);
        pack2(va.x, vb.x, vh[0], vl[0]); pack2(va.y, vb.y, vh[1], vl[1]);
        pack2(va.z, vb.z, vh[2], vl[2]); pack2(va.w, vb.w, vh[3], vl[3]);
        const int o = rp * 72 + 4 * cc;
        *(uint4*)&skh[o] = make_uint4(kh[0], kh[1], kh[2], kh[3]);
        *(uint4*)&skl[o] = make_uint4(kl[0], kl[1], kl[2], kl[3]);
        *(uint4*)&svh[o] = make_uint4(vh[0], vh[1], vh[2], vh[3]);
        *(uint4*)&svl[o] = make_uint4(vl[0], vl[1], vl[2], vl[3]);
    }
    __syncthreads();

    const int m0 = 16 * w;

    float acc[8][4];
#pragma unroll
    for (int j = 0; j < 8; j++)
#pragma unroll
        for (int p = 0; p < 4; p++) acc[j][p] = 0.0f;

#pragma unroll
    for (int ks = 0; ks < 4; ks++) {       // 4 x k16 = 64 seq rows
        const int kp0 = ks * 8;
        uint32_t ah[4], al[4];
        ah[0] = skh[(kp0 + tig)     * 72 + m0 + g];
        ah[1] = skh[(kp0 + tig)     * 72 + m0 + g + 8];
        ah[2] = skh[(kp0 + tig + 4) * 72 + m0 + g];
        ah[3] = skh[(kp0 + tig + 4) * 72 + m0 + g + 8];
        al[0] = skl[(kp0 + tig)     * 72 + m0 + g];
        al[1] = skl[(kp0 + tig)     * 72 + m0 + g + 8];
        al[2] = skl[(kp0 + tig + 4) * 72 + m0 + g];
        al[3] = skl[(kp0 + tig + 4) * 72 + m0 + g + 8];
#pragma unroll
        for (int j = 0; j < 8; j++) {
            const int n0 = 8 * j;
            uint32_t bh[2], bl[2];
            bh[0] = svh[(kp0 + tig)     * 72 + n0 + g];
            bh[1] = svh[(kp0 + tig + 4) * 72 + n0 + g];
            bl[0] = svl[(kp0 + tig)     * 72 + n0 + g];
            bl[1] = svl[(kp0 + tig + 4) * 72 + n0 + g];
            mma16(acc[j], ah, bh);
            mma16(acc[j], ah, bl);
            mma16(acc[j], al, bh);
        }
    }

    float* P = g_partials + ((size_t)c * BATCH + b) * (DIM * DIM);
#pragma unroll
    for (int j = 0; j < 8; j++) {
        const int col = 8 * j + 2 * tig;
        *(float2*)&P[(m0 + g)     * DIM + col] = make_float2(acc[j][0], acc[j][1]);
        *(float2*)&P[(m0 + g + 8) * DIM + col] = make_float2(acc[j][2], acc[j][3]);
    }
}

// ---------------------------------------------------------------------------
// Kernel 2a: tree reduce level 1 (64 -> 8 groups). 65536 threads, BW-bound.
// ---------------------------------------------------------------------------
__global__ __launch_bounds__(256) void reduce_a_kernel()
{
    const int idx = blockIdx.x * 256 + threadIdx.x;
    const int grp = idx >> 13;
    const int o   = idx & 8191;
    const float4* P = (const float4*)g_partials;
    float4 s0 = make_float4(0.f, 0.f, 0.f, 0.f);
    float4 s1 = make_float4(0.f, 0.f, 0.f, 0.f);
#pragma unroll
    for (int i = 0; i < 8; i += 2) {
        const float4 a = P[(size_t)(grp * 8 + i)     * 8192 + o];
        const float4 e = P[(size_t)(grp * 8 + i + 1) * 8192 + o];
        s0.x += a.x; s0.y += a.y; s0.z += a.z; s0.w += a.w;
        s1.x += e.x; s1.y += e.y; s1.z += e.z; s1.w += e.w;
    }
    ((float4*)g_p2)[(size_t)grp * 8192 + o] =
        make_float4(s0.x + s1.x, s0.y + s1.y, s0.z + s1.z, s0.w + s1.w);
}

// ---------------------------------------------------------------------------
// Kernel 2b: tree reduce level 2 (L2-hot). 8192 threads.
// ---------------------------------------------------------------------------
__global__ __launch_bounds__(256) void reduce_b_kernel()
{
    const int o = blockIdx.x * 256 + threadIdx.x;
    const float4* P = (const float4*)g_p2;
    float4 s0 = make_float4(0.f, 0.f, 0.f, 0.f);
    float4 s1 = make_float4(0.f, 0.f, 0.f, 0.f);
#pragma unroll
    for (int i = 0; i < NGRP; i += 2) {
        const float4 a = P[(size_t)i       * 8192 + o];
        const float4 e = P[(size_t)(i + 1) * 8192 + o];
        s0.x += a.x; s0.y += a.y; s0.z += a.z; s0.w += a.w;
        s1.x += e.x; s1.y += e.y; s1.z += e.z; s1.w += e.w;
    }
    ((float4*)g_M)[o] = make_float4(s0.x + s1.x, s0.y + s1.y,
                                    s0.z + s1.z, s0.w + s1.w);
}

// ---------------------------------------------------------------------------
// Kernel 3: out = scale * rope(Q) @ M[b].  1024 CTAs x 128 thr; CTA = 32
// q-rows x 64 cols. q packed [dim-pair][row] stride 40 (40%32=8); M packed
// [dim-pair][n] stride 72. 4 warps: row-half (w&1) x col-half (w>>1, 4 js).
// ---------------------------------------------------------------------------
__global__ __launch_bounds__(128) void qm_kernel(
    const float* __restrict__ Q, const float* __restrict__ FQ,
    float* __restrict__ OUT)
{
    const int b  = blockIdx.y;
    const int rc = blockIdx.x;           // 32-row chunk, 0..127
    const int t  = threadIdx.x;
    const int w  = t >> 5;
    const int lane = t & 31;
    const int g = lane >> 2;
    const int tig = lane & 3;

    __shared__ uint32_t sMh[32 * 72], sMl[32 * 72];   // 9.2 KB each
    __shared__ uint32_t sqh[32 * 40], sql[32 * 40];   // 5.1 KB each

    // ---- stage + split M[b]: items = (dim-pair 0..31, col4 0..15) ----
    {
        const float4* M4 = (const float4*)(g_M + (size_t)b * DIM * DIM);
#pragma unroll
        for (int u = 0; u < 4; u++) {
            const int f  = t + 128 * u;
            const int kp = f >> 4;       // dim pair
            const int cc = f & 15;
            const float4 ma = M4[(2 * kp)     * 16 + cc];
            const float4 mb = M4[(2 * kp + 1) * 16 + cc];
            uint32_t h[4], l[4];
            pack2(ma.x, mb.x, h[0], l[0]); pack2(ma.y, mb.y, h[1], l[1]);
            pack2(ma.z, mb.z, h[2], l[2]); pack2(ma.w, mb.w, h[3], l[3]);
            const int o = kp * 72 + 4 * cc;
            *(uint4*)&sMh[o] = make_uint4(h[0], h[1], h[2], h[3]);
            *(uint4*)&sMl[o] = make_uint4(l[0], l[1], l[2], l[3]);
        }
    }

    // ---- stage + rope + split 32 q rows: item = (dim-pair, row) ----
    {
        const float2* Q2  = (const float2*)(Q + ((size_t)b * SEQ + rc * 32) * DIM);
        const float2* FQ2 = (const float2*)(FQ + (size_t)rc * 32 * DIM);
#pragma unroll
        for (int u = 0; u < 8; u++) {
            const int f   = t + 128 * u;
            const int row = f & 31;
            const int kp  = f >> 5;      // dim pair 0..31
            const float2 qv = Q2[row * 32 + kp];
            const float2 fv = FQ2[row * 32 + kp];
            const float x0 = qv.x * fv.x - qv.y * fv.y;
            const float x1 = qv.x * fv.y + qv.y * fv.x;
            uint32_t h, l;
            pack2(x0, x1, h, l);
            sqh[kp * 40 + row] = h;
            sql[kp * 40 + row] = l;
        }
    }
    __syncthreads();

    const int m0s = 16 * (w & 1);
    const int nh  = 32 * (w >> 1);

    float cc2[4][4];
#pragma unroll
    for (int j = 0; j < 4; j++)
#pragma unroll
        for (int p = 0; p < 4; p++) cc2[j][p] = 0.0f;

#pragma unroll
    for (int ks = 0; ks < 4; ks++) {     // 4 x k16 = 64 dims
        const int kp0 = ks * 8;
        uint32_t ah[4], al[4];
        ah[0] = sqh[(kp0 + tig)     * 40 + m0s + g];
        ah[1] = sqh[(kp0 + tig)     * 40 + m0s + g + 8];
        ah[2] = sqh[(kp0 + tig + 4) * 40 + m0s + g];
        ah[3] = sqh[(kp0 + tig + 4) * 40 + m0s + g + 8];
        al[0] = sql[(kp0 + tig)     * 40 + m0s + g];
        al[1] = sql[(kp0 + tig)     * 40 + m0s + g + 8];
        al[2] = sql[(kp0 + tig + 4) * 40 + m0s + g];
        al[3] = sql[(kp0 + tig + 4) * 40 + m0s + g + 8];
#pragma unroll
        for (int j = 0; j < 4; j++) {
            const int n0 = nh + 8 * j;
            uint32_t bh[2], bl[2];
            bh[0] = sMh[(kp0 + tig)     * 72 + n0 + g];
            bh[1] = sMh[(kp0 + tig + 4) * 72 + n0 + g];
            bl[0] = sMl[(kp0 + tig)     * 72 + n0 + g];
            bl[1] = sMl[(kp0 + tig + 4) * 72 + n0 + g];
            mma16(cc2[j], ah, bh);
            mma16(cc2[j], ah, bl);
            mma16(cc2[j], al, bh);
        }
    }

    // ---- write 16 rows x 32 cols for this warp ----
    const float scale = 0.125f;   // 1/sqrt(64)
    float* O = OUT + ((size_t)b * SEQ + rc * 32) * DIM;
#pragma unroll
    for (int j = 0; j < 4; j++) {
        const int col = nh + 8 * j + 2 * tig;
        *(float2*)&O[(size_t)(m0s + g)     * DIM + col] =
            make_float2(cc2[j][0] * scale, cc2[j][1] * scale);
        *(float2*)&O[(size_t)(m0s + g + 8) * DIM + col] =
            make_float2(cc2[j][2] * scale, cc2[j][3] * scale);
    }
}

// ---------------------------------------------------------------------------
extern "C" void kernel_launch(void* const* d_in, const int* in_sizes, int n_in,
                              void* d_out, int out_size)
{
    const float* q  = (const float*)d_in[0];
    const float* k  = (const float*)d_in[1];
    const float* v  = (const float*)d_in[2];
    const float* fq = (const float*)d_in[3];
    const float* fk = (const float*)d_in[4];
    const float* fv = (const float*)d_in[5];
    float* out = (float*)d_out;

    kv_outer_kernel<<<dim3(NC, BATCH), 128>>>(k, v, fk, fv);
    reduce_a_kernel<<<256, 256>>>();
    reduce_b_kernel<<<32, 256>>>();
    qm_kernel<<<dim3(SEQ / 32, BATCH), 128>>>(q, fq, out);
}

// round 16
// speedup vs baseline: 1.5969x; 1.4015x over previous
#include <cuda_runtime.h>
#include <cuda_bf16.h>
#include <cstdint>

// B=8, SEQ=4096, DIM=64.
// out = scale * rope(Q) @ (rope(K)^T @ rope(V))   (associativity; no softmax)
// scale = 1/sqrt(64) = 0.125
// Tensor path: mma.sync.m16n8k16 BF16, 2-way split (3 MMAs) -> ~6e-6 accuracy.

#define BATCH  8
#define SEQ    4096
#define DIM    64
#define NC     64          // k1 chunks per batch (64 rows each)
#define CH     64
#define NGRP   8

__device__ float g_partials[NC * BATCH * DIM * DIM];   // 8 MB
__device__ float g_p2[NGRP * BATCH * DIM * DIM];       // 1 MB
__device__ float g_M[BATCH * DIM * DIM];               // 128 KB

// ---------------------------------------------------------------------------
__device__ __forceinline__ float4 rope4(float4 x, float4 f) {
    float4 o;
    o.x = x.x * f.x - x.y * f.y;  o.y = x.x * f.y + x.y * f.x;
    o.z = x.z * f.z - x.w * f.w;  o.w = x.z * f.w + x.w * f.z;
    return o;
}
// bf16 MMA: D(16x8) += A(16x16) * B(16x8)
__device__ __forceinline__ void mma16(float* c, const uint32_t* a, const uint32_t* b) {
    asm volatile(
        "mma.sync.aligned.m16n8k16.row.col.f32.bf16.bf16.f32 "
        "{%0,%1,%2,%3}, {%4,%5,%6,%7}, {%8,%9}, {%0,%1,%2,%3};\n"
        : "+f"(c[0]), "+f"(c[1]), "+f"(c[2]), "+f"(c[3])
        : "r"(a[0]), "r"(a[1]), "r"(a[2]), "r"(a[3]), "r"(b[0]), "r"(b[1]));
}
// pack (x0 -> lo half, x1 -> hi half) as bf16x2; also emit lo-residual word.
__device__ __forceinline__ void pack2(float x0, float x1, uint32_t& h, uint32_t& l) {
    asm("cvt.rn.bf16x2.f32 %0, %1, %2;" : "=r"(h) : "f"(x1), "f"(x0));
    const float u0 = __uint_as_float(h << 16);
    const float u1 = __uint_as_float(h & 0xFFFF0000u);
    const float l0 = x0 - u0;
    const float l1 = x1 - u1;
    asm("cvt.rn.bf16x2.f32 %0, %1, %2;" : "=r"(l) : "f"(l1), "f"(l0));
}

// ---------------------------------------------------------------------------
// Kernel 1 (R15-verified): partial M = rope(K)^T @ rope(V) over 64 rows.
// 512 CTAs x 128 thr, 4 warps; warp w = M rows 16w..16w+15 x all 64 cols.
// K packed [seq-pair][dim] stride 72 (fragment LDS = 8*tig+g permutation);
// V packed [seq-pair][n], same stride.
// ---------------------------------------------------------------------------
__global__ __launch_bounds__(128) void kv_outer_kernel(
    const float* __restrict__ K, const float* __restrict__ V,
    const float* __restrict__ FK, const float* __restrict__ FV)
{
    const int b = blockIdx.y;
    const int c = blockIdx.x;
    const int t = threadIdx.x;
    const int w = t >> 5;
    const int lane = t & 31;
    const int g = lane >> 2;
    const int tig = lane & 3;

    __shared__ uint32_t skh[32 * 72], skl[32 * 72];   // A hi/lo: 9.2 KB each
    __shared__ uint32_t svh[32 * 72], svl[32 * 72];   // B hi/lo

    const float4* K4  = (const float4*)(K + (size_t)b * SEQ * DIM);
    const float4* V4  = (const float4*)(V + (size_t)b * SEQ * DIM);
    const float4* FK4 = (const float4*)FK;
    const float4* FV4 = (const float4*)FV;

    // staging: 512 items = (32 row-pairs x 16 col4), 4 per thread
#pragma unroll
    for (int u = 0; u < 4; u++) {
        const int f  = t + 128 * u;
        const int rp = f >> 4;          // seq row-pair 0..31
        const int cc = f & 15;          // float4 column
        const int r0 = (c * CH + 2 * rp) * 16 + cc;
        const float4 ka = rope4(K4[r0],      FK4[r0]);
        const float4 kb = rope4(K4[r0 + 16], FK4[r0 + 16]);
        const float4 va = rope4(V4[r0],      FV4[r0]);
        const float4 vb = rope4(V4[r0 + 16], FV4[r0 + 16]);
        uint32_t kh[4], kl[4], vh[4], vl[4];
        pack2(ka.x, kb.x, kh[0], kl[0]); pack2(ka.y, kb.y, kh[1], kl[1]);
        pack2(ka.z, kb.z, kh[2], kl[2]); pack2(ka.w, kb.w, kh[3], kl[3]);
        pack2(va.x, vb.x, vh[0], vl[0]); pack2(va.y, vb.y, vh[1], vl[1]);
        pack2(va.z, vb.z, vh[2], vl[2]); pack2(va.w, vb.w, vh[3], vl[3]);
        const int o = rp * 72 + 4 * cc;
        *(uint4*)&skh[o] = make_uint4(kh[0], kh[1], kh[2], kh[3]);
        *(uint4*)&skl[o] = make_uint4(kl[0], kl[1], kl[2], kl[3]);
        *(uint4*)&svh[o] = make_uint4(vh[0], vh[1], vh[2], vh[3]);
        *(uint4*)&svl[o] = make_uint4(vl[0], vl[1], vl[2], vl[3]);
    }
    __syncthreads();

    const int m0 = 16 * w;

    float acc[8][4];
#pragma unroll
    for (int j = 0; j < 8; j++)
#pragma unroll
        for (int p = 0; p < 4; p++) acc[j][p] = 0.0f;

#pragma unroll
    for (int ks = 0; ks < 4; ks++) {       // 4 x k16 = 64 seq rows
        const int kp0 = ks * 8;
        uint32_t ah[4], al[4];
        ah[0] = skh[(kp0 + tig)     * 72 + m0 + g];
        ah[1] = skh[(kp0 + tig)     * 72 + m0 + g + 8];
        ah[2] = skh[(kp0 + tig + 4) * 72 + m0 + g];
        ah[3] = skh[(kp0 + tig + 4) * 72 + m0 + g + 8];
        al[0] = skl[(kp0 + tig)     * 72 + m0 + g];
        al[1] = skl[(kp0 + tig)     * 72 + m0 + g + 8];
        al[2] = skl[(kp0 + tig + 4) * 72 + m0 + g];
        al[3] = skl[(kp0 + tig + 4) * 72 + m0 + g + 8];
#pragma unroll
        for (int j = 0; j < 8; j++) {
            const int n0 = 8 * j;
            uint32_t bh[2], bl[2];
            bh[0] = svh[(kp0 + tig)     * 72 + n0 + g];
            bh[1] = svh[(kp0 + tig + 4) * 72 + n0 + g];
            bl[0] = svl[(kp0 + tig)     * 72 + n0 + g];
            bl[1] = svl[(kp0 + tig + 4) * 72 + n0 + g];
            mma16(acc[j], ah, bh);
            mma16(acc[j], ah, bl);
            mma16(acc[j], al, bh);
        }
    }

    float* P = g_partials + ((size_t)c * BATCH + b) * (DIM * DIM);
#pragma unroll
    for (int j = 0; j < 8; j++) {
        const int col = 8 * j + 2 * tig;
        *(float2*)&P[(m0 + g)     * DIM + col] = make_float2(acc[j][0], acc[j][1]);
        *(float2*)&P[(m0 + g + 8) * DIM + col] = make_float2(acc[j][2], acc[j][3]);
    }
}

// ---------------------------------------------------------------------------
// Kernel 2a: tree reduce level 1 (64 -> 8 groups). BW-bound.
// ---------------------------------------------------------------------------
__global__ __launch_bounds__(256) void reduce_a_kernel()
{
    const int idx = blockIdx.x * 256 + threadIdx.x;
    const int grp = idx >> 13;
    const int o   = idx & 8191;
    const float4* P = (const float4*)g_partials;
    float4 s0 = make_float4(0.f, 0.f, 0.f, 0.f);
    float4 s1 = make_float4(0.f, 0.f, 0.f, 0.f);
#pragma unroll
    for (int i = 0; i < 8; i += 2) {
        const float4 a = P[(size_t)(grp * 8 + i)     * 8192 + o];
        const float4 e = P[(size_t)(grp * 8 + i + 1) * 8192 + o];
        s0.x += a.x; s0.y += a.y; s0.z += a.z; s0.w += a.w;
        s1.x += e.x; s1.y += e.y; s1.z += e.z; s1.w += e.w;
    }
    ((float4*)g_p2)[(size_t)grp * 8192 + o] =
        make_float4(s0.x + s1.x, s0.y + s1.y, s0.z + s1.z, s0.w + s1.w);
}

// ---------------------------------------------------------------------------
// Kernel 2b: tree reduce level 2 (L2-hot).
// ---------------------------------------------------------------------------
__global__ __launch_bounds__(256) void reduce_b_kernel()
{
    const int o = blockIdx.x * 256 + threadIdx.x;
    const float4* P = (const float4*)g_p2;
    float4 s0 = make_float4(0.f, 0.f, 0.f, 0.f);
    float4 s1 = make_float4(0.f, 0.f, 0.f, 0.f);
#pragma unroll
    for (int i = 0; i < NGRP; i += 2) {
        const float4 a = P[(size_t)i       * 8192 + o];
        const float4 e = P[(size_t)(i + 1) * 8192 + o];
        s0.x += a.x; s0.y += a.y; s0.z += a.z; s0.w += a.w;
        s1.x += e.x; s1.y += e.y; s1.z += e.z; s1.w += e.w;
    }
    ((float4*)g_M)[o] = make_float4(s0.x + s1.x, s0.y + s1.y,
                                    s0.z + s1.z, s0.w + s1.w);
}

// ---------------------------------------------------------------------------
// Kernel 3: out = scale * rope(Q) @ M[b].  1024 CTAs x 128 thr; CTA = 32
// q-rows x 64 cols. q staged COALESCED into raw fp32 rows (stride 68,
// R12/13-proven layout); A fragments packed in-loop from LDS.64 of rope'd
// dim-pairs. M staged bf16 hi/lo [dim-pair][n] stride 72 (R15-proven).
// 4 warps: row-half (w&1) x col-half (w>>1, 4 j-tiles).
// ---------------------------------------------------------------------------
__global__ __launch_bounds__(128) void qm_kernel(
    const float* __restrict__ Q, const float* __restrict__ FQ,
    float* __restrict__ OUT)
{
    const int b  = blockIdx.y;
    const int rc = blockIdx.x;           // 32-row chunk, 0..127
    const int t  = threadIdx.x;
    const int w  = t >> 5;
    const int lane = t & 31;
    const int g = lane >> 2;
    const int tig = lane & 3;

    __shared__ uint32_t sMh[32 * 72], sMl[32 * 72];   // 9.2 KB each
    __shared__ float sq[32 * 68];                      // 8.7 KB raw rope'd q

    // ---- stage + split M[b]: items = (dim-pair 0..31, col4 0..15) ----
    {
        const float4* M4 = (const float4*)(g_M + (size_t)b * DIM * DIM);
#pragma unroll
        for (int u = 0; u < 4; u++) {
            const int f  = t + 128 * u;
            const int kp = f >> 4;       // dim pair
            const int cc = f & 15;
            const float4 ma = M4[(2 * kp)     * 16 + cc];
            const float4 mb = M4[(2 * kp + 1) * 16 + cc];
            uint32_t h[4], l[4];
            pack2(ma.x, mb.x, h[0], l[0]); pack2(ma.y, mb.y, h[1], l[1]);
            pack2(ma.z, mb.z, h[2], l[2]); pack2(ma.w, mb.w, h[3], l[3]);
            const int o = kp * 72 + 4 * cc;
            *(uint4*)&sMh[o] = make_uint4(h[0], h[1], h[2], h[3]);
            *(uint4*)&sMl[o] = make_uint4(l[0], l[1], l[2], l[3]);
        }
    }

    // ---- stage 32 rope'd q rows, coalesced float4 (proven pattern) ----
    {
        const float4* Q4  = (const float4*)(Q + ((size_t)b * SEQ + rc * 32) * DIM);
        const float4* F4  = (const float4*)(FQ + (size_t)rc * 32 * DIM);
#pragma unroll
        for (int u = 0; u < 4; u++) {
            const int f  = t + 128 * u;
            const int rr = f >> 4, cc = f & 15;
            *(float4*)&sq[rr * 68 + 4 * cc] = rope4(Q4[f], F4[f]);
        }
    }
    __syncthreads();

    const int m0s = 16 * (w & 1);
    const int nh  = 32 * (w >> 1);

    float cc2[4][4];
#pragma unroll
    for (int j = 0; j < 4; j++)
#pragma unroll
        for (int p = 0; p < 4; p++) cc2[j][p] = 0.0f;

#pragma unroll
    for (int ks = 0; ks < 4; ks++) {     // 4 x k16 = 64 dims
        const int kp0 = ks * 8;
        // A fragments: pack dim-pairs (adjacent fp32) from raw q rows
        uint32_t ah[4], al[4];
        {
            const float2 q0 = *(const float2*)&sq[(m0s + g)     * 68 + 2 * (kp0 + tig)];
            const float2 q1 = *(const float2*)&sq[(m0s + g + 8) * 68 + 2 * (kp0 + tig)];
            const float2 q2 = *(const float2*)&sq[(m0s + g)     * 68 + 2 * (kp0 + tig + 4)];
            const float2 q3 = *(const float2*)&sq[(m0s + g + 8) * 68 + 2 * (kp0 + tig + 4)];
            pack2(q0.x, q0.y, ah[0], al[0]);
            pack2(q1.x, q1.y, ah[1], al[1]);
            pack2(q2.x, q2.y, ah[2], al[2]);
            pack2(q3.x, q3.y, ah[3], al[3]);
        }
#pragma unroll
        for (int j = 0; j < 4; j++) {
            const int n0 = nh + 8 * j;
            uint32_t bh[2], bl[2];
            bh[0] = sMh[(kp0 + tig)     * 72 + n0 + g];
            bh[1] = sMh[(kp0 + tig + 4) * 72 + n0 + g];
            bl[0] = sMl[(kp0 + tig)     * 72 + n0 + g];
            bl[1] = sMl[(kp0 + tig + 4) * 72 + n0 + g];
            mma16(cc2[j], ah, bh);
            mma16(cc2[j], ah, bl);
            mma16(cc2[j], al, bh);
        }
    }

    // ---- write 16 rows x 32 cols for this warp ----
    const float scale = 0.125f;   // 1/sqrt(64)
    float* O = OUT + ((size_t)b * SEQ + rc * 32) * DIM;
#pragma unroll
    for (int j = 0; j < 4; j++) {
        const int col = nh + 8 * j + 2 * tig;
        *(float2*)&O[(size_t)(m0s + g)     * DIM + col] =
            make_float2(cc2[j][0] * scale, cc2[j][1] * scale);
        *(float2*)&O[(size_t)(m0s + g + 8) * DIM + col] =
            make_float2(cc2[j][2] * scale, cc2[j][3] * scale);
    }
}

// ---------------------------------------------------------------------------
extern "C" void kernel_launch(void* const* d_in, const int* in_sizes, int n_in,
                              void* d_out, int out_size)
{
    const float* q  = (const float*)d_in[0];
    const float* k  = (const float*)d_in[1];
    const float* v  = (const float*)d_in[2];
    const float* fq = (const float*)d_in[3];
    const float* fk = (const float*)d_in[4];
    const float* fv = (const float*)d_in[5];
    float* out = (float*)d_out;

    kv_outer_kernel<<<dim3(NC, BATCH), 128>>>(k, v, fk, fv);
    reduce_a_kernel<<<256, 256>>>();
    reduce_b_kernel<<<32, 256>>>();
    qm_kernel<<<dim3(SEQ / 32, BATCH), 128>>>(q, fq, out);
}